// round 15
// baseline (speedup 1.0000x reference)
#include <cuda_runtime.h>

namespace {

constexpr int Wd  = 512;
constexpr int Hd  = 512;
constexpr int TH  = 16;           // output rows per CTA
constexpr int VW  = 528;          // padded vbuf width (8 zero cols each side)
constexpr int NT  = 256;
constexpr int WIN = TH + 14;      // 30-row input window

__device__ __forceinline__ unsigned long long pack2(float lo, float hi) {
    unsigned long long r;
    asm("mov.b64 %0, {%1, %2};" : "=l"(r) : "f"(lo), "f"(hi));
    return r;
}
__device__ __forceinline__ void fma2(unsigned long long& d,
                                     unsigned long long a,
                                     unsigned long long b) {
    asm("fma.rn.f32x2 %0, %1, %2, %0;" : "+l"(d) : "l"(a), "l"(b));
}
__host__ __device__ constexpr int widx(int j) { return j < 8 ? j : 14 - j; }

union F4 {
    float4 f;
    unsigned long long u[2];
    float s[4];
};

__global__ void __launch_bounds__(NT, 4)
gauss_kernel(const float* __restrict__ x, const float* __restrict__ sigma,
             float* __restrict__ out, int C)
{
    __shared__ float vbuf[TH * VW];   // 33792 B -> 4 CTAs/SM

    const int strip = blockIdx.x;
    const int ch    = blockIdx.y;
    const int b     = blockIdx.z;
    const int tid   = threadIdx.x;
    const int r0    = strip * TH;

    // ---- zero-fill column halos (words [0,8) and [520,528) per row) ----
    if (tid < 64) {
        const int row = tid >> 2;
        const int q   = tid & 3;
        const int cc  = (q < 2) ? q * 4 : 520 + (q - 2) * 4;
        *reinterpret_cast<float4*>(&vbuf[row * VW + cc]) =
            make_float4(0.f, 0.f, 0.f, 0.f);
    }

    // ---- symmetric 1D Gaussian weights (8 distinct), packed broadcast ----
    const float sg  = sigma[b];
    const float inv = 1.0f / (2.0f * sg * sg + 1e-8f);
    float w[8];
    float s = 0.0f;
#pragma unroll
    for (int i = 0; i < 8; ++i) {
        const float a = (float)(7 - i);
        w[i] = __expf(-a * a * inv);
        s += (i < 7) ? 2.0f * w[i] : w[i];
    }
    const float rs = 1.0f / s;
    unsigned long long wp[8];
#pragma unroll
    for (int i = 0; i < 8; ++i) { w[i] *= rs; wp[i] = pack2(w[i], w[i]); }

    const size_t img = (size_t)(b * C + ch) * (Hd * Wd);
    const float* __restrict__ xp = x + img;
    float* __restrict__       op = out + img;

    // ================= Stage 1: vertical, global -> vbuf =================
    // thread: 2 cols x 16 rows; 30-row sliding input window
    {
        const int c0 = tid * 2;
        const int rbase = r0 - 7;

        unsigned long long acc[TH];
#pragma unroll
        for (int o = 0; o < TH; ++o) acc[o] = 0ull;

        if (rbase >= 0 && rbase + WIN - 1 < Hd) {
            const float* p = xp + (size_t)rbase * Wd + c0;
#pragma unroll
            for (int rr = 0; rr < WIN; ++rr) {
                const unsigned long long v =
                    *reinterpret_cast<const unsigned long long*>(p + rr * Wd);
#pragma unroll
                for (int o = 0; o < TH; ++o) {
                    const int j = rr - o;
                    if (j >= 0 && j < 15) fma2(acc[o], v, wp[widx(j)]);
                }
            }
        } else {
            const float* colp = xp + c0;
#pragma unroll
            for (int rr = 0; rr < WIN; ++rr) {
                const int gr = rbase + rr;
                if ((unsigned)gr < (unsigned)Hd) {
                    const unsigned long long v =
                        *reinterpret_cast<const unsigned long long*>(
                            colp + (size_t)gr * Wd);
#pragma unroll
                    for (int o = 0; o < TH; ++o) {
                        const int j = rr - o;
                        if (j >= 0 && j < 15) fma2(acc[o], v, wp[widx(j)]);
                    }
                }
            }
        }
#pragma unroll
        for (int o = 0; o < TH; ++o)
            *reinterpret_cast<unsigned long long*>(&vbuf[o * VW + 8 + c0]) =
                acc[o];
    }
    __syncthreads();

    // ================= Stage 2: horizontal, vbuf -> global =================
    // thread: 8-col chunk x 4 rows. Window f[0..23] = cols c0-8..c0+15 held
    // as 6 quads; explicit consume-then-reload blocks (R13 discipline) keep
    // the live set ~56 regs. Even-s pairs free from LDS.128 register pairs;
    // 11 odd-s pairs packed on the fly. 24 LDS.128/thread vs 40 in the
    // 4-col version.
    {
        const int chunk = tid & 63;       // 0..63 : 8-col chunk
        const int rsel  = tid >> 6;       // 0..3
        const int gc0   = chunk * 8;
        const float* basep = &vbuf[8 + gc0];

        F4 v0, v1, v2, v3, v4, v5;
        {
            const float* rp = basep + rsel * VW;
            v0.f = *reinterpret_cast<const float4*>(rp - 8);
            v1.f = *reinterpret_cast<const float4*>(rp - 4);
            v2.f = *reinterpret_cast<const float4*>(rp);
            v3.f = *reinterpret_cast<const float4*>(rp + 4);
            v4.f = *reinterpret_cast<const float4*>(rp + 8);
            v5.f = *reinterpret_cast<const float4*>(rp + 12);
        }

#pragma unroll
        for (int t = 0; t < 4; ++t) {
            const int row = rsel + 4 * t;
            const float* rpn = basep + (row + 4) * VW;   // next row (t+1)
            // acc pair p covers outputs (c0+2p, c0+2p+1); pair s feeds p
            // with weight j = s - 2p - 1 when j in [0,14]
            unsigned long long a0 = 0ull, a1 = 0ull, a2 = 0ull, a3 = 0ull;

            // --- block v0: s=1..3 ---
            {
                const unsigned long long P1 = pack2(v0.s[1], v0.s[2]);
                const unsigned long long P3 = pack2(v0.s[3], v1.s[0]);
                fma2(a0, P1, wp[widx(0)]);            // s=1
                fma2(a0, v0.u[1], wp[widx(1)]);       // s=2
                fma2(a0, P3, wp[widx(2)]);            // s=3
                fma2(a1, P3, wp[widx(0)]);
            }
            if (t < 3) v0.f = *reinterpret_cast<const float4*>(rpn - 8);

            // --- block v1: s=4..7 ---
            {
                const unsigned long long P5 = pack2(v1.s[1], v1.s[2]);
                const unsigned long long P7 = pack2(v1.s[3], v2.s[0]);
                fma2(a0, v1.u[0], wp[widx(3)]);       // s=4
                fma2(a1, v1.u[0], wp[widx(1)]);
                fma2(a0, P5, wp[widx(4)]);            // s=5
                fma2(a1, P5, wp[widx(2)]);
                fma2(a2, P5, wp[widx(0)]);
                fma2(a0, v1.u[1], wp[widx(5)]);       // s=6
                fma2(a1, v1.u[1], wp[widx(3)]);
                fma2(a2, v1.u[1], wp[widx(1)]);
                fma2(a0, P7, wp[widx(6)]);            // s=7
                fma2(a1, P7, wp[widx(4)]);
                fma2(a2, P7, wp[widx(2)]);
                fma2(a3, P7, wp[widx(0)]);
            }
            if (t < 3) v1.f = *reinterpret_cast<const float4*>(rpn - 4);

            // --- block v2: s=8..11 ---
            {
                const unsigned long long P9  = pack2(v2.s[1], v2.s[2]);
                const unsigned long long P11 = pack2(v2.s[3], v3.s[0]);
                fma2(a0, v2.u[0], wp[widx(7)]);       // s=8
                fma2(a1, v2.u[0], wp[widx(5)]);
                fma2(a2, v2.u[0], wp[widx(3)]);
                fma2(a3, v2.u[0], wp[widx(1)]);
                fma2(a0, P9, wp[widx(8)]);            // s=9
                fma2(a1, P9, wp[widx(6)]);
                fma2(a2, P9, wp[widx(4)]);
                fma2(a3, P9, wp[widx(2)]);
                fma2(a0, v2.u[1], wp[widx(9)]);       // s=10
                fma2(a1, v2.u[1], wp[widx(7)]);
                fma2(a2, v2.u[1], wp[widx(5)]);
                fma2(a3, v2.u[1], wp[widx(3)]);
                fma2(a0, P11, wp[widx(10)]);          // s=11
                fma2(a1, P11, wp[widx(8)]);
                fma2(a2, P11, wp[widx(6)]);
                fma2(a3, P11, wp[widx(4)]);
            }
            if (t < 3) v2.f = *reinterpret_cast<const float4*>(rpn);

            // --- block v3: s=12..15 ---
            {
                const unsigned long long P13 = pack2(v3.s[1], v3.s[2]);
                const unsigned long long P15 = pack2(v3.s[3], v4.s[0]);
                fma2(a0, v3.u[0], wp[widx(11)]);      // s=12
                fma2(a1, v3.u[0], wp[widx(9)]);
                fma2(a2, v3.u[0], wp[widx(7)]);
                fma2(a3, v3.u[0], wp[widx(5)]);
                fma2(a0, P13, wp[widx(12)]);          // s=13
                fma2(a1, P13, wp[widx(10)]);
                fma2(a2, P13, wp[widx(8)]);
                fma2(a3, P13, wp[widx(6)]);
                fma2(a0, v3.u[1], wp[widx(13)]);      // s=14
                fma2(a1, v3.u[1], wp[widx(11)]);
                fma2(a2, v3.u[1], wp[widx(9)]);
                fma2(a3, v3.u[1], wp[widx(7)]);
                fma2(a0, P15, wp[widx(14)]);          // s=15
                fma2(a1, P15, wp[widx(12)]);
                fma2(a2, P15, wp[widx(10)]);
                fma2(a3, P15, wp[widx(8)]);
            }
            if (t < 3) v3.f = *reinterpret_cast<const float4*>(rpn + 4);

            // --- block v4: s=16..19 ---
            {
                const unsigned long long P17 = pack2(v4.s[1], v4.s[2]);
                const unsigned long long P19 = pack2(v4.s[3], v5.s[0]);
                fma2(a1, v4.u[0], wp[widx(13)]);      // s=16
                fma2(a2, v4.u[0], wp[widx(11)]);
                fma2(a3, v4.u[0], wp[widx(9)]);
                fma2(a1, P17, wp[widx(14)]);          // s=17
                fma2(a2, P17, wp[widx(12)]);
                fma2(a3, P17, wp[widx(10)]);
                fma2(a2, v4.u[1], wp[widx(13)]);      // s=18
                fma2(a3, v4.u[1], wp[widx(11)]);
                fma2(a2, P19, wp[widx(14)]);          // s=19
                fma2(a3, P19, wp[widx(12)]);
            }
            if (t < 3) v4.f = *reinterpret_cast<const float4*>(rpn + 8);

            // --- block v5: s=20,21 ---
            {
                const unsigned long long P21 = pack2(v5.s[1], v5.s[2]);
                fma2(a3, v5.u[0], wp[widx(13)]);      // s=20
                fma2(a3, P21, wp[widx(14)]);          // s=21
            }
            if (t < 3) v5.f = *reinterpret_cast<const float4*>(rpn + 12);

            float* po = op + (size_t)(r0 + row) * Wd + gc0;
            *reinterpret_cast<ulonglong2*>(po)     = make_ulonglong2(a0, a1);
            *reinterpret_cast<ulonglong2*>(po + 4) = make_ulonglong2(a2, a3);
        }
    }
}

}  // namespace

extern "C" void kernel_launch(void* const* d_in, const int* in_sizes, int n_in,
                              void* d_out, int out_size) {
    const float* x     = (const float*)d_in[0];
    const float* sigma = (const float*)d_in[1];
    float* out         = (float*)d_out;

    const int B = in_sizes[1];                      // 32
    const int C = in_sizes[0] / (B * Hd * Wd);      // 3

    dim3 grid(Hd / TH, C, B);                       // 32 x 3 x 32 = 3072
    gauss_kernel<<<grid, NT>>>(x, sigma, out, C);
}

// round 16
// speedup vs baseline: 1.1144x; 1.1144x over previous
#include <cuda_runtime.h>

namespace {

constexpr int Wd  = 512;
constexpr int Hd  = 512;
constexpr int TH  = 16;           // output rows per CTA
constexpr int VW  = 528;          // padded vbuf width (8 zero cols each side)
constexpr int NT  = 256;
constexpr int WIN = TH + 14;      // 30-row input window

__device__ __forceinline__ unsigned long long pack2(float lo, float hi) {
    unsigned long long r;
    asm("mov.b64 %0, {%1, %2};" : "=l"(r) : "f"(lo), "f"(hi));
    return r;
}
__device__ __forceinline__ void fma2(unsigned long long& d,
                                     unsigned long long a,
                                     unsigned long long b) {
    asm("fma.rn.f32x2 %0, %1, %2, %0;" : "+l"(d) : "l"(a), "l"(b));
}
__host__ __device__ constexpr int widx(int j) { return j < 8 ? j : 14 - j; }

union F4 {
    float4 f;
    unsigned long long u[2];
    float s[4];
};

__global__ void __launch_bounds__(NT, 4)
gauss_kernel(const float* __restrict__ x, const float* __restrict__ sigma,
             float* __restrict__ out, int C)
{
    __shared__ float vbuf[TH * VW];   // 33792 B -> 4 CTAs/SM

    const int strip = blockIdx.x;
    const int ch    = blockIdx.y;
    const int b     = blockIdx.z;
    const int tid   = threadIdx.x;
    const int r0    = strip * TH;

    // ---- zero-fill column halos (words [0,8) and [520,528) per row) ----
    if (tid < 64) {
        const int row = tid >> 2;
        const int q   = tid & 3;
        const int cc  = (q < 2) ? q * 4 : 520 + (q - 2) * 4;
        *reinterpret_cast<float4*>(&vbuf[row * VW + cc]) =
            make_float4(0.f, 0.f, 0.f, 0.f);
    }

    // ---- symmetric 1D Gaussian weights (8 distinct), packed broadcast ----
    const float sg  = sigma[b];
    const float inv = 1.0f / (2.0f * sg * sg + 1e-8f);
    float w[8];
    float s = 0.0f;
#pragma unroll
    for (int i = 0; i < 8; ++i) {
        const float a = (float)(7 - i);
        w[i] = __expf(-a * a * inv);
        s += (i < 7) ? 2.0f * w[i] : w[i];
    }
    const float rs = 1.0f / s;
    unsigned long long wp[8];
#pragma unroll
    for (int i = 0; i < 8; ++i) { w[i] *= rs; wp[i] = pack2(w[i], w[i]); }

    const size_t img = (size_t)(b * C + ch) * (Hd * Wd);
    const float* __restrict__ xp = x + img;
    float* __restrict__       op = out + img;

    // ================= Stage 1: vertical, global -> vbuf =================
    // thread: 2 cols x 16 rows; 30-row sliding input window
    {
        const int c0 = tid * 2;
        const int rbase = r0 - 7;

        unsigned long long acc[TH];
#pragma unroll
        for (int o = 0; o < TH; ++o) acc[o] = 0ull;

        if (rbase >= 0 && rbase + WIN - 1 < Hd) {
            const float* p = xp + (size_t)rbase * Wd + c0;
#pragma unroll
            for (int rr = 0; rr < WIN; ++rr) {
                const unsigned long long v =
                    *reinterpret_cast<const unsigned long long*>(p + rr * Wd);
#pragma unroll
                for (int o = 0; o < TH; ++o) {
                    const int j = rr - o;
                    if (j >= 0 && j < 15) fma2(acc[o], v, wp[widx(j)]);
                }
            }
        } else {
            const float* colp = xp + c0;
#pragma unroll
            for (int rr = 0; rr < WIN; ++rr) {
                const int gr = rbase + rr;
                if ((unsigned)gr < (unsigned)Hd) {
                    const unsigned long long v =
                        *reinterpret_cast<const unsigned long long*>(
                            colp + (size_t)gr * Wd);
#pragma unroll
                    for (int o = 0; o < TH; ++o) {
                        const int j = rr - o;
                        if (j >= 0 && j < 15) fma2(acc[o], v, wp[widx(j)]);
                    }
                }
            }
        }
#pragma unroll
        for (int o = 0; o < TH; ++o)
            *reinterpret_cast<unsigned long long*>(&vbuf[o * VW + 8 + c0]) =
                acc[o];
    }
    __syncthreads();

    // ================= Stage 2: horizontal, vbuf -> global =================
    // thread: 4-col chunk x 8 rows. Even-s input pairs come directly from
    // LDS.128 register pairs (no pack); only 9 odd-s pairs are packed.
    {
        const int chunk = tid & 127;
        const int rsel  = tid >> 7;
        const int gc0   = chunk * 4;
        const float* basep = &vbuf[8 + gc0];

#pragma unroll
        for (int t = 0; t < 8; ++t) {
            const int row = rsel + 2 * t;
            const float* rp = basep + row * VW;

            F4 v[5];
#pragma unroll
            for (int k = 0; k < 5; ++k)
                v[k].f = *reinterpret_cast<const float4*>(rp - 8 + 4 * k);

            // odd-s pairs O[k] = (f[2k+1], f[2k+2]), k = 0..8
            unsigned long long O[9];
#pragma unroll
            for (int k = 0; k < 9; ++k) {
                const int i0 = 2 * k + 1;
                const int i1 = 2 * k + 2;
                O[k] = pack2(v[i0 >> 2].s[i0 & 3], v[i1 >> 2].s[i1 & 3]);
            }

            unsigned long long ap0 = 0ull, ap1 = 0ull;
#pragma unroll
            for (int sidx = 1; sidx <= 17; ++sidx) {
                const unsigned long long P =
                    (sidx & 1) ? O[(sidx - 1) >> 1]
                               : v[sidx >> 2].u[(sidx >> 1) & 1];
                if (sidx <= 15) fma2(ap0, P, wp[widx(sidx - 1)]);
                if (sidx >= 3)  fma2(ap1, P, wp[widx(sidx - 3)]);
            }
            *reinterpret_cast<ulonglong2*>(op + (size_t)(r0 + row) * Wd + gc0) =
                make_ulonglong2(ap0, ap1);
        }
    }
}

}  // namespace

extern "C" void kernel_launch(void* const* d_in, const int* in_sizes, int n_in,
                              void* d_out, int out_size) {
    const float* x     = (const float*)d_in[0];
    const float* sigma = (const float*)d_in[1];
    float* out         = (float*)d_out;

    const int B = in_sizes[1];                      // 32
    const int C = in_sizes[0] / (B * Hd * Wd);      // 3

    dim3 grid(Hd / TH, C, B);                       // 32 x 3 x 32 = 3072
    gauss_kernel<<<grid, NT>>>(x, sigma, out, C);
}